// round 5
// baseline (speedup 1.0000x reference)
#include <cuda_runtime.h>
#include <cstdint>

#define K_DIM 4096
#define N_DIM 8192
#define INFCAP 100.0f
#define BP_EPS 1e-4f
#define NSM 148

// ---------------- scratch (no allocation allowed) ----------------
__device__ float g_colsum[N_DIM];   // sum_k Hxs[k,n]
__device__ float g_colsum2[N_DIM];  // sum_k Hxs_new[k,n] (atomically accumulated by k_main)
__device__ float g_prior[N_DIM];    // clip(dope+phi+colsum, +-INFCAP)
__device__ float g_dope[N_DIM];     // doping LLR

__device__ __forceinline__ float tanh_approx(float x) {
    float r;
    asm("tanh.approx.f32 %0, %1;" : "=f"(r) : "f"(x));
    return r;
}

// ---------------- K0: zero accumulators ----------------
__global__ void k_zero() {
    int i = blockIdx.x * blockDim.x + threadIdx.x;
    if (i < N_DIM) { g_colsum[i] = 0.f; g_colsum2[i] = 0.f; }
}

// ---------------- K1: column sum of Hxs ----------------
__global__ __launch_bounds__(256) void k_colsum(const float* __restrict__ M) {
    const int ROWS = 64;
    int cbase = blockIdx.x * 1024 + threadIdx.x * 4;
    int r0 = blockIdx.y * ROWS;
    const float4* p = (const float4*)(M + (size_t)r0 * N_DIM + cbase);
    float4 a = make_float4(0.f, 0.f, 0.f, 0.f);
#pragma unroll 8
    for (int r = 0; r < ROWS; r++) {
        float4 v = p[(size_t)r * (N_DIM / 4)];
        a.x += v.x; a.y += v.y; a.z += v.z; a.w += v.w;
    }
    atomicAdd(&g_colsum[cbase + 0], a.x);
    atomicAdd(&g_colsum[cbase + 1], a.y);
    atomicAdd(&g_colsum[cbase + 2], a.z);
    atomicAdd(&g_colsum[cbase + 3], a.w);
}

// ---------------- K1b: dope / phi / prior ----------------
__global__ void k_prior(const float* __restrict__ ps, const float* __restrict__ Min) {
    int n = blockIdx.x * blockDim.x + threadIdx.x;
    if (n >= N_DIM) return;
    float p0 = ps[2 * n], p1 = ps[2 * n + 1];
    float pn = p1 / (p0 + p1);
    float dope = logf(1.f - pn) - logf(pn);
    float m0 = Min[2 * n], m1 = Min[2 * n + 1];
    float mn = m1 / (m0 + m1);
    float phi = logf(1.f - mn) - logf(mn);
    g_dope[n] = dope;
    float pr = dope + phi + g_colsum[n];
    g_prior[n] = fminf(fmaxf(pr, -INFCAP), INFCAP);
}

// ---------------- K2: persistent main kernel ----------------
// grid = 148 (one CTA per SM), block = 1024. Each thread owns 8 fixed columns
// (two float4 groups: [4*tid, 4*tid+4) and [4096+4*tid, ...)). Per row:
//   load Hxs/H -> t (registers) -> block product reduce -> outputs + register
//   column-sum accumulation. Next row's loads are issued BEFORE the reduction
//   so DRAM stays busy through the barriers. Column sums flushed with 8
//   atomicAdds per thread at the end (1.2M total, ~4us).
__device__ __forceinline__ float bp_elem(float t, float prod, float s) {
    if (t == 0.f) return 0.f;                        // zero-mask -> arctanh(0) -> 0
    float y = s * __fdividef(prod, t);               // (1-2x) * prodtanhm / tanhm
    y = fminf(fmaxf(y, -1.f), 1.f);
    float r = __logf(__fdividef(1.f + y, 1.f - y));  // 2*atanh(y); +-inf at endpoints
    return fminf(fmaxf(r, -1.f), 1.f);               // clip absorbs inf
}

__device__ __forceinline__ float t_elem(int h, float pr, float hx) {
    return tanh_approx(0.5f * (h ? (pr + BP_EPS - hx) : -hx));
}

__global__ __launch_bounds__(1024, 1) void k_main(const float* __restrict__ Hxs,
                                                  const int* __restrict__ H,
                                                  const int* __restrict__ x,
                                                  float* __restrict__ out_Hxs) {
    __shared__ float warp_prod[2][32];
    int tid = threadIdx.x;
    int wid = tid >> 5, lane = tid & 31;

    const float4* pr4 = (const float4*)g_prior;
    float4 prA = pr4[tid];
    float4 prB = pr4[1024 + tid];
    float4 csA = make_float4(0.f, 0.f, 0.f, 0.f);
    float4 csB = make_float4(0.f, 0.f, 0.f, 0.f);

    int k = blockIdx.x;
    float4 hxA = {}, hxB = {}; int4 hA = {}, hB = {}; float s = 0.f;
    if (k < K_DIM) {
        const float4* hx4 = (const float4*)(Hxs + (size_t)k * N_DIM);
        const int4*   h4  = (const int4*)(H + (size_t)k * N_DIM);
        hxA = hx4[tid]; hxB = hx4[1024 + tid];
        hA  = h4[tid];  hB  = h4[1024 + tid];
        s = (float)(1 - 2 * x[k]);
    }
    int parity = 0;

    while (k < K_DIM) {
        // ---- compute t for current row (registers only) ----
        float4 tA, tB;
        tA.x = t_elem(hA.x, prA.x, hxA.x);
        tA.y = t_elem(hA.y, prA.y, hxA.y);
        tA.z = t_elem(hA.z, prA.z, hxA.z);
        tA.w = t_elem(hA.w, prA.w, hxA.w);
        tB.x = t_elem(hB.x, prB.x, hxB.x);
        tB.y = t_elem(hB.y, prB.y, hxB.y);
        tB.z = t_elem(hB.z, prB.z, hxB.z);
        tB.w = t_elem(hB.w, prB.w, hxB.w);

        float p = ((tA.x == 0.f) ? 1.f : tA.x) * ((tA.y == 0.f) ? 1.f : tA.y)
                * ((tA.z == 0.f) ? 1.f : tA.z) * ((tA.w == 0.f) ? 1.f : tA.w)
                * ((tB.x == 0.f) ? 1.f : tB.x) * ((tB.y == 0.f) ? 1.f : tB.y)
                * ((tB.z == 0.f) ? 1.f : tB.z) * ((tB.w == 0.f) ? 1.f : tB.w);

        // ---- issue prefetch for next row BEFORE the reduction barriers ----
        int kn = k + NSM;
        float4 nhxA = {}, nhxB = {}; int4 nhA = {}, nhB = {}; float ns = 0.f;
        if (kn < K_DIM) {
            const float4* hx4 = (const float4*)(Hxs + (size_t)kn * N_DIM);
            const int4*   h4  = (const int4*)(H + (size_t)kn * N_DIM);
            nhxA = hx4[tid]; nhxB = hx4[1024 + tid];
            nhA  = h4[tid];  nhB  = h4[1024 + tid];
            ns = (float)(1 - 2 * x[kn]);
        }

        // ---- block product reduction (double-buffered smem stage) ----
#pragma unroll
        for (int off = 16; off; off >>= 1) p *= __shfl_xor_sync(0xffffffffu, p, off);
        if (lane == 0) warp_prod[parity][wid] = p;
        __syncthreads();
        if (wid == 0) {
            float q = warp_prod[parity][lane];
#pragma unroll
            for (int off = 16; off; off >>= 1) q *= __shfl_xor_sync(0xffffffffu, q, off);
            if (lane == 0) warp_prod[parity][0] = q;
        }
        __syncthreads();
        float prod = warp_prod[parity][0];
        parity ^= 1;

        // ---- outputs + register column-sum accumulation ----
        float4* o4 = (float4*)(out_Hxs + (size_t)k * N_DIM);
        float4 oA, oB;
        oA.x = bp_elem(tA.x, prod, s); csA.x += oA.x;
        oA.y = bp_elem(tA.y, prod, s); csA.y += oA.y;
        oA.z = bp_elem(tA.z, prod, s); csA.z += oA.z;
        oA.w = bp_elem(tA.w, prod, s); csA.w += oA.w;
        oB.x = bp_elem(tB.x, prod, s); csB.x += oB.x;
        oB.y = bp_elem(tB.y, prod, s); csB.y += oB.y;
        oB.z = bp_elem(tB.z, prod, s); csB.z += oB.z;
        oB.w = bp_elem(tB.w, prod, s); csB.w += oB.w;
        o4[tid] = oA;
        o4[1024 + tid] = oB;

        // ---- rotate prefetched row into place ----
        k = kn;
        hxA = nhxA; hxB = nhxB; hA = nhA; hB = nhB; s = ns;
    }

    // ---- flush column partial sums (8 atomics per thread) ----
    int cA = tid * 4;
    int cB = 4096 + tid * 4;
    atomicAdd(&g_colsum2[cA + 0], csA.x);
    atomicAdd(&g_colsum2[cA + 1], csA.y);
    atomicAdd(&g_colsum2[cA + 2], csA.z);
    atomicAdd(&g_colsum2[cA + 3], csA.w);
    atomicAdd(&g_colsum2[cB + 0], csB.x);
    atomicAdd(&g_colsum2[cB + 1], csB.y);
    atomicAdd(&g_colsum2[cB + 2], csB.z);
    atomicAdd(&g_colsum2[cB + 3], csB.w);
}

// ---------------- K3: output beliefs ----------------
__global__ void k_out(float* __restrict__ out_M) {
    int n = blockIdx.x * blockDim.x + threadIdx.x;
    if (n >= N_DIM) return;
    float z = (1.f - tanhf((g_colsum2[n] + g_dope[n]) * 0.5f)) * 0.5f;
    out_M[2 * n + 0] = 1.f - z;
    out_M[2 * n + 1] = z;
}

extern "C" void kernel_launch(void* const* d_in, const int* in_sizes, int n_in,
                              void* d_out, int out_size) {
    const float* ps  = (const float*)d_in[0];
    const float* Min = (const float*)d_in[1];
    const float* Hxs = (const float*)d_in[2];
    const int*   x   = (const int*)d_in[3];
    const int*   H   = (const int*)d_in[4];

    float* out     = (float*)d_out;
    float* out_M   = out;                 // M_out [N,2] first
    float* out_Hxs = out + 2 * N_DIM;     // Hxs_new [K,N] second

    k_zero<<<N_DIM / 256, 256>>>();
    k_colsum<<<dim3(N_DIM / 1024, K_DIM / 64), 256>>>(Hxs);
    k_prior<<<N_DIM / 256, 256>>>(ps, Min);
    k_main<<<NSM, 1024>>>(Hxs, H, x, out_Hxs);
    k_out<<<N_DIM / 256, 256>>>(out_M);
}

// round 6
// speedup vs baseline: 1.2503x; 1.2503x over previous
#include <cuda_runtime.h>
#include <cstdint>

#define K_DIM 4096
#define N_DIM 8192
#define INFCAP 100.0f
#define BP_EPS 1e-4f

// ---------------- scratch (no allocation allowed) ----------------
__device__ float g_colsum[N_DIM];   // sum_k Hxs[k,n]
__device__ float g_colsum2[N_DIM];  // sum_k Hxs_new[k,n]
__device__ float g_prior[N_DIM];    // clip(dope+phi+colsum, +-INFCAP)
__device__ float g_dope[N_DIM];     // doping LLR
__device__ float g_prod[K_DIM];     // per-row tanh product (0 => row output is exactly 0)

__device__ __forceinline__ float tanh_approx(float x) {
    float r;
    asm("tanh.approx.f32 %0, %1;" : "=f"(r) : "f"(x));
    return r;
}

// ---------------- K0: zero accumulators ----------------
__global__ void k_zero() {
    int i = blockIdx.x * blockDim.x + threadIdx.x;
    if (i < N_DIM) { g_colsum[i] = 0.f; g_colsum2[i] = 0.f; }
}

// ---------------- K1: column sum of Hxs ----------------
__global__ __launch_bounds__(256) void k_colsum(const float* __restrict__ M) {
    const int ROWS = 64;
    int cbase = blockIdx.x * 1024 + threadIdx.x * 4;
    int r0 = blockIdx.y * ROWS;
    const float4* p = (const float4*)(M + (size_t)r0 * N_DIM + cbase);
    float4 a = make_float4(0.f, 0.f, 0.f, 0.f);
#pragma unroll 8
    for (int r = 0; r < ROWS; r++) {
        float4 v = p[(size_t)r * (N_DIM / 4)];
        a.x += v.x; a.y += v.y; a.z += v.z; a.w += v.w;
    }
    atomicAdd(&g_colsum[cbase + 0], a.x);
    atomicAdd(&g_colsum[cbase + 1], a.y);
    atomicAdd(&g_colsum[cbase + 2], a.z);
    atomicAdd(&g_colsum[cbase + 3], a.w);
}

// ---------------- K1b: dope / phi / prior ----------------
__global__ void k_prior(const float* __restrict__ ps, const float* __restrict__ Min) {
    int n = blockIdx.x * blockDim.x + threadIdx.x;
    if (n >= N_DIM) return;
    float p0 = ps[2 * n], p1 = ps[2 * n + 1];
    float pn = p1 / (p0 + p1);
    float dope = logf(1.f - pn) - logf(pn);
    float m0 = Min[2 * n], m1 = Min[2 * n + 1];
    float mn = m1 / (m0 + m1);
    float phi = logf(1.f - mn) - logf(mn);
    g_dope[n] = dope;
    float pr = dope + phi + g_colsum[n];
    g_prior[n] = fminf(fmaxf(pr, -INFCAP), INFCAP);
}

// ---------------- K2: main row kernel ----------------
// One CTA (512 threads) per check row. Sweep 1: stream the row, compute the
// tanh product only (no smem staging). If prod == 0 (fp32 underflow of ~4096
// |t|<1 factors -- the common case), every output of the row is EXACTLY
// clip(2*atanh(+-0)) = 0, so sweep 2 is a pure zero-write and the row
// contributes nothing to colsum2. Otherwise (general inputs) a fallback
// re-reads the row (L1/L2-warm) and computes the exact leave-one-out values.
__device__ __forceinline__ float bp_elem(float t, float prod, float s) {
    if (t == 0.f) return 0.f;                        // zero-mask -> arctanh(0) -> 0
    float y = s * __fdividef(prod, t);               // (1-2x) * prodtanhm / tanhm
    y = fminf(fmaxf(y, -1.f), 1.f);
    float r = __logf(__fdividef(1.f + y, 1.f - y));  // 2*atanh(y); +-inf at endpoints
    return fminf(fmaxf(r, -1.f), 1.f);               // clip absorbs inf
}

__device__ __forceinline__ float t_elem(int h, float pr, float hx) {
    return tanh_approx(0.5f * (h ? (pr + BP_EPS - hx) : -hx));
}

__global__ __launch_bounds__(512) void k_main(const float* __restrict__ Hxs,
                                              const int* __restrict__ H,
                                              const int* __restrict__ x,
                                              float* __restrict__ out_Hxs) {
    __shared__ float warp_prod[16];
    int k = blockIdx.x;
    int tid = threadIdx.x;

    const float4* hx4 = (const float4*)(Hxs + (size_t)k * N_DIM);
    const int4*   h4  = (const int4*)(H + (size_t)k * N_DIM);
    const float4* pr4 = (const float4*)g_prior;

    // ---- sweep 1: row product only ----
    float p = 1.f;
#pragma unroll
    for (int i = 0; i < 4; i++) {
        int idx = tid + i * 512;
        float4 hx = hx4[idx];
        int4   h  = h4[idx];
        float4 pr = pr4[idx];
        float tx = t_elem(h.x, pr.x, hx.x);
        float ty = t_elem(h.y, pr.y, hx.y);
        float tz = t_elem(h.z, pr.z, hx.z);
        float tw = t_elem(h.w, pr.w, hx.w);
        p *= ((tx == 0.f) ? 1.f : tx) * ((ty == 0.f) ? 1.f : ty)
           * ((tz == 0.f) ? 1.f : tz) * ((tw == 0.f) ? 1.f : tw);
    }

    // ---- block product reduction ----
#pragma unroll
    for (int off = 16; off; off >>= 1) p *= __shfl_xor_sync(0xffffffffu, p, off);
    if ((tid & 31) == 0) warp_prod[tid >> 5] = p;
    __syncthreads();
    if (tid < 16) {
        float q = warp_prod[tid];
#pragma unroll
        for (int off = 8; off; off >>= 1) q *= __shfl_xor_sync(0x0000ffffu, q, off);
        if (tid == 0) warp_prod[0] = q;
    }
    __syncthreads();
    float prod = warp_prod[0];
    if (tid == 0) g_prod[k] = prod;

    float4* o4 = (float4*)(out_Hxs + (size_t)k * N_DIM);
    if (prod == 0.f) {
        // ---- fast path: outputs are exactly zero ----
        float4 z = make_float4(0.f, 0.f, 0.f, 0.f);
#pragma unroll
        for (int i = 0; i < 4; i++) o4[tid + i * 512] = z;
    } else {
        // ---- fallback (general correctness): recompute t and full bp_elem ----
        float s = (float)(1 - 2 * x[k]);
#pragma unroll
        for (int i = 0; i < 4; i++) {
            int idx = tid + i * 512;
            float4 hx = hx4[idx];
            int4   h  = h4[idx];
            float4 pr = pr4[idx];
            float4 o;
            o.x = bp_elem(t_elem(h.x, pr.x, hx.x), prod, s);
            o.y = bp_elem(t_elem(h.y, pr.y, hx.y), prod, s);
            o.z = bp_elem(t_elem(h.z, pr.z, hx.z), prod, s);
            o.w = bp_elem(t_elem(h.w, pr.w, hx.w), prod, s);
            o4[idx] = o;
        }
    }
}

// ---------------- K3: column sum of Hxs_new, skipping all-zero rows ----------------
__global__ __launch_bounds__(256) void k_colsum2(const float* __restrict__ M) {
    const int ROWS = 64;
    int cbase = blockIdx.x * 1024 + threadIdx.x * 4;
    int r0 = blockIdx.y * ROWS;
    const float4* p = (const float4*)(M + (size_t)r0 * N_DIM + cbase);
    float4 a = make_float4(0.f, 0.f, 0.f, 0.f);
    bool any = false;
    for (int r = 0; r < ROWS; r++) {
        if (g_prod[r0 + r] != 0.f) {      // zero-product rows are exactly 0: skip
            any = true;
            float4 v = p[(size_t)r * (N_DIM / 4)];
            a.x += v.x; a.y += v.y; a.z += v.z; a.w += v.w;
        }
    }
    if (any) {
        atomicAdd(&g_colsum2[cbase + 0], a.x);
        atomicAdd(&g_colsum2[cbase + 1], a.y);
        atomicAdd(&g_colsum2[cbase + 2], a.z);
        atomicAdd(&g_colsum2[cbase + 3], a.w);
    }
}

// ---------------- K4: output beliefs ----------------
__global__ void k_out(float* __restrict__ out_M) {
    int n = blockIdx.x * blockDim.x + threadIdx.x;
    if (n >= N_DIM) return;
    float z = (1.f - tanhf((g_colsum2[n] + g_dope[n]) * 0.5f)) * 0.5f;
    out_M[2 * n + 0] = 1.f - z;
    out_M[2 * n + 1] = z;
}

extern "C" void kernel_launch(void* const* d_in, const int* in_sizes, int n_in,
                              void* d_out, int out_size) {
    const float* ps  = (const float*)d_in[0];
    const float* Min = (const float*)d_in[1];
    const float* Hxs = (const float*)d_in[2];
    const int*   x   = (const int*)d_in[3];
    const int*   H   = (const int*)d_in[4];

    float* out     = (float*)d_out;
    float* out_M   = out;                 // M_out [N,2] first
    float* out_Hxs = out + 2 * N_DIM;     // Hxs_new [K,N] second

    k_zero<<<N_DIM / 256, 256>>>();
    k_colsum<<<dim3(N_DIM / 1024, K_DIM / 64), 256>>>(Hxs);
    k_prior<<<N_DIM / 256, 256>>>(ps, Min);
    k_main<<<K_DIM, 512>>>(Hxs, H, x, out_Hxs);
    k_colsum2<<<dim3(N_DIM / 1024, K_DIM / 64), 256>>>(out_Hxs);
    k_out<<<N_DIM / 256, 256>>>(out_M);
}